// round 16
// baseline (speedup 1.0000x reference)
#include <cuda_runtime.h>
#include <cuda_fp16.h>
#include <cstdint>

#define T_STEPS 64
#define B_ENV 128
#define L_TOK 64
#define E_DIM 256
#define H_DIM 32
#define N_TOT (T_STEPS * B_ENV)

__device__ float g_M[65536];
__device__ float g_WeffT[65536];
__device__ float g_W2[32768];
__device__ float g_bias[128];
__device__ unsigned short g_Mt16[65536]; // fp16 of M^T [j][i]
__device__ float g_xw[(size_t)N_TOT * 256]; // attention-pooled features
__device__ float g_xg[(size_t)N_TOT * 128];
__device__ int g_mode;

// ---------------- helpers ----------------
__device__ __forceinline__ uint32_t smem_u32(const void* p) {
    uint32_t a;
    asm("{ .reg .u64 t; cvta.to.shared.u64 t, %1; cvt.u32.u64 %0, t; }" : "=r"(a) : "l"(p));
    return a;
}
__device__ __forceinline__ void ldm4(uint32_t* r, uint32_t a) {
    asm volatile("ldmatrix.sync.aligned.m8n8.x4.shared.b16 {%0,%1,%2,%3}, [%4];"
        : "=r"(r[0]), "=r"(r[1]), "=r"(r[2]), "=r"(r[3]) : "r"(a));
}
__device__ __forceinline__ void mma_fp16(float* d, const uint32_t* a, const uint32_t* b) {
    asm volatile("mma.sync.aligned.m16n8k16.row.col.f32.f16.f16.f32 "
        "{%0,%1,%2,%3}, {%4,%5,%6,%7}, {%8,%9}, {%0,%1,%2,%3};"
        : "+f"(d[0]), "+f"(d[1]), "+f"(d[2]), "+f"(d[3])
        : "r"(a[0]), "r"(a[1]), "r"(a[2]), "r"(a[3]), "r"(b[0]), "r"(b[1]));
}
__device__ __forceinline__ uint32_t pack_h2(__half lo, __half hi) {
    __half2 p = __halves2half2(lo, hi);
    return *(uint32_t*)&p;
}
__device__ __forceinline__ void cp16(uint32_t dst, const void* src) {
    asm volatile("cp.async.cg.shared.global [%0], [%1], 16;" :: "r"(dst), "l"(src));
}
#define CP_COMMIT() asm volatile("cp.async.commit_group;" ::: "memory")
#define CP_WAIT0()  asm volatile("cp.async.wait_group 0;" ::: "memory")

// ---------------- prep1: M (b<64), WeffT (b>=64) ----------------
__global__ void __launch_bounds__(256) prep1(const float* __restrict__ ipw, const float* __restrict__ opw) {
    __shared__ float As[32][33], Bs[32][33];
    const int b = blockIdx.x, tid = threadIdx.x, tx = tid & 31, ty = tid >> 5;
    float acc[4] = {0.f, 0.f, 0.f, 0.f};
    if (b < 64) {
        int i0 = (b >> 3) * 32, j0 = (b & 7) * 32;
        const float *Wq = ipw, *Wk = ipw + 65536;
        for (int e0 = 0; e0 < 256; e0 += 32) {
#pragma unroll
            for (int r = 0; r < 4; r++) {
                int e = ty + 8 * r;
                As[e][tx] = Wq[(e0 + e) * 256 + i0 + tx];
                Bs[e][tx] = Wk[(e0 + e) * 256 + j0 + tx];
            }
            __syncthreads();
#pragma unroll 8
            for (int e = 0; e < 32; e++) {
                float bv = Bs[e][tx];
#pragma unroll
                for (int r = 0; r < 4; r++) acc[r] += As[e][ty + 8 * r] * bv;
            }
            __syncthreads();
        }
#pragma unroll
        for (int r = 0; r < 4; r++) g_M[(i0 + ty + 8 * r) * 256 + j0 + tx] = acc[r];
    } else {
        int t = b - 64, j0 = (t >> 3) * 32, f0 = (t & 7) * 32;
        const float* Wv = ipw + 131072;
        for (int e0 = 0; e0 < 256; e0 += 32) {
#pragma unroll
            for (int r = 0; r < 4; r++) {
                int e = ty + 8 * r;
                As[e][tx] = Wv[(e0 + e) * 256 + j0 + tx];
                Bs[tx][e] = opw[(f0 + e) * 256 + e0 + tx];
            }
            __syncthreads();
#pragma unroll 8
            for (int e = 0; e < 32; e++) {
                float bv = Bs[e][tx];
#pragma unroll
                for (int r = 0; r < 4; r++) acc[r] += As[e][ty + 8 * r] * bv;
            }
            __syncthreads();
        }
#pragma unroll
        for (int r = 0; r < 4; r++) g_WeffT[(j0 + ty + 8 * r) * 256 + f0 + tx] = acc[r];
    }
}

// ------- prep2: Mt fp16 (b<64), W2 (64..95), bias + mask-mode (96) -------
__global__ void __launch_bounds__(256) prep2(const float* __restrict__ wih,
                                             const float* __restrict__ bih,
                                             const float* __restrict__ bhh,
                                             const void* __restrict__ mask) {
    __shared__ float As[32][33], Bs[32][33];
    const int b = blockIdx.x, tid = threadIdx.x, tx = tid & 31, ty = tid >> 5;
    if (b < 64) {
        int i0 = (b >> 3) * 32, j0 = (b & 7) * 32;
#pragma unroll
        for (int r = 0; r < 4; r++) As[ty + 8 * r][tx] = g_M[(i0 + ty + 8 * r) * 256 + j0 + tx];
        __syncthreads();
#pragma unroll
        for (int r = 0; r < 4; r++) {
            int jj = ty + 8 * r;
            __half h = __float2half_rn(As[tx][jj]);
            g_Mt16[(j0 + jj) * 256 + i0 + tx] = *(unsigned short*)&h;
        }
        return;
    }
    if (b < 96) {
        int t = b - 64, j0 = (t >> 2) * 32, g0 = (t & 3) * 32;
        float acc[4] = {0.f, 0.f, 0.f, 0.f};
        for (int f0 = 0; f0 < 256; f0 += 32) {
#pragma unroll
            for (int r = 0; r < 4; r++) {
                int e = ty + 8 * r;
                As[tx][e] = g_WeffT[(j0 + e) * 256 + f0 + tx];
                Bs[tx][e] = wih[(g0 + e) * 256 + f0 + tx];
            }
            __syncthreads();
#pragma unroll 8
            for (int f = 0; f < 32; f++) {
                float bv = Bs[f][tx];
#pragma unroll
                for (int r = 0; r < 4; r++) acc[r] += As[f][ty + 8 * r] * bv;
            }
            __syncthreads();
        }
#pragma unroll
        for (int r = 0; r < 4; r++) g_W2[(j0 + ty + 8 * r) * 128 + g0 + tx] = acc[r];
        return;
    }
    if (tid < 128) g_bias[tid] = bih[tid] + bhh[tid];
    __shared__ int sf, sg;
    if (!tid) { sf = 0; sg = 0; }
    __syncthreads();
    const unsigned* mw = (const unsigned*)mask;
    int f = 0, g = 0;
    for (int i = tid; i < 4096; i += 256) {
        unsigned v = mw[i];
        if (v == 0x3F800000u) f = 1;
        if (v > 1u) g = 1;
    }
    if (f) atomicOr(&sf, 1);
    if (g) atomicOr(&sg, 1);
    __syncthreads();
    if (!tid) g_mode = sf ? 2 : (sg ? 1 : 0);
}

// ---------------- attention: full fp16, 1 sample/CTA, 3 CTAs/SM --------------
#define XH_OFF   0        /* x fp16: 64 x 512 */
#define STG_OFF  32768    /* Mt16 chunk: 64 x 512 */
#define TSH_OFF  65536    /* ts fp16: 64 x 128 */
#define SMEM_SZ  73728
#define SC_OFF   STG_OFF           /* f32 [64][68] after GEMMs */
#define DF_OFF   TSH_OFF           /* 64 f */
#define WGT_OFF  (TSH_OFF + 256)   /* 64 f */
#define XWP_OFF  (TSH_OFF + 2048)  /* 512 f partials */

__global__ void __launch_bounds__(256, 3) attn_mma(const float* __restrict__ x,
                                                   const void* __restrict__ mask) {
    extern __shared__ char smem[];
    const uint32_t sb = smem_u32(smem);
    const int tid = threadIdx.x, lane = tid & 31, w = tid >> 5;
    const int n = blockIdx.x;

    for (int u = tid; u < 2048; u += 256) {
        int row = u >> 5, c16 = (u & 31) << 4;
        uint32_t d = STG_OFF + row * 512 + (c16 ^ ((row & 7) << 4));
        cp16(sb + d, (const uint4*)g_Mt16 + u);
    }
    CP_COMMIT();

    const float2* xb = (const float2*)(x + (size_t)n * (L_TOK * E_DIM));
    for (int idx = tid; idx < 8192; idx += 256) {
        int r = idx >> 7, cp = idx & 127;
        float2 v = xb[idx];
        uint32_t boff = (uint32_t)(r * 512 + ((cp * 4) ^ ((r & 7) << 4)));
        *(uint32_t*)(smem + XH_OFF + boff) =
            pack_h2(__float2half_rn(v.x), __float2half_rn(v.y));
    }
    CP_WAIT0();
    __syncthreads();

    const int mg = w >> 1, ng = w & 1;
    const int arow = mg * 16 + (lane & 15);
    const uint32_t a_rot = (arow & 7) << 4, a_klo = (lane >> 4) << 4;
    const uint32_t axh = sb + XH_OFF + arow * 512;
    const uint32_t ath = sb + TSH_OFF + arow * 128;
    const int br0 = ng * 32 + (lane & 7) + ((lane & 16) >> 1), br1 = br0 + 16;
    const uint32_t b_rot0 = (br0 & 7) << 4, b_rot1 = (br1 & 7) << 4;
    const uint32_t bklo = ((lane >> 3) & 1) << 4;

    float acc2[4][4];
#pragma unroll
    for (int nt = 0; nt < 4; nt++)
#pragma unroll
        for (int q = 0; q < 4; q++) acc2[nt][q] = 0.f;

    for (int ch = 0; ch < 4; ch++) {
        float acc1[4][4];
#pragma unroll
        for (int nt = 0; nt < 4; nt++)
#pragma unroll
            for (int q = 0; q < 4; q++) acc1[nt][q] = 0.f;
        const uint32_t sg0 = sb + STG_OFF + br0 * 512, sg1 = sb + STG_OFF + br1 * 512;
#pragma unroll 4
        for (int ks = 0; ks < 16; ks++) {
            uint32_t kb = ks * 32;
            uint32_t Ah[4], B0[4], B1[4];
            ldm4(Ah, axh + ((kb + a_klo) ^ a_rot));
            ldm4(B0, sg0 + ((kb + bklo) ^ b_rot0));
            ldm4(B1, sg1 + ((kb + bklo) ^ b_rot1));
            mma_fp16(acc1[0], Ah, B0); mma_fp16(acc1[1], Ah, B0 + 2);
            mma_fp16(acc1[2], Ah, B1); mma_fp16(acc1[3], Ah, B1 + 2);
        }
#pragma unroll
        for (int nt = 0; nt < 4; nt++) {
            int col = ng * 32 + nt * 8 + 2 * (lane & 3);
            int r0 = mg * 16 + (lane >> 2);
#pragma unroll
            for (int hh = 0; hh < 2; hh++) {
                int rr = r0 + 8 * hh;
                uint32_t boff = (uint32_t)(rr * 128 + ((col * 2) ^ ((rr & 7) << 4)));
                *(uint32_t*)(smem + TSH_OFF + boff) =
                    pack_h2(__float2half_rn(acc1[nt][2 * hh]),
                            __float2half_rn(acc1[nt][2 * hh + 1]));
            }
        }
        __syncthreads();

        if (ch < 3) {
            for (int u = tid; u < 2048; u += 256) {
                int row = u >> 5, c16 = (u & 31) << 4;
                uint32_t d = STG_OFF + row * 512 + (c16 ^ ((row & 7) << 4));
                cp16(sb + d, (const uint4*)(g_Mt16 + (ch + 1) * 16384) + u);
            }
            CP_COMMIT();
        }

        const uint32_t bxh0 = sb + XH_OFF + br0 * 512, bxh1 = sb + XH_OFF + br1 * 512;
#pragma unroll
        for (int ks = 0; ks < 4; ks++) {
            uint32_t kb = ks * 32, xc = ch * 128 + kb + bklo;
            uint32_t Ah[4], Bh0[4], Bh1[4];
            ldm4(Ah, ath + ((kb + a_klo) ^ a_rot));
            ldm4(Bh0, bxh0 + (xc ^ b_rot0));
            ldm4(Bh1, bxh1 + (xc ^ b_rot1));
            mma_fp16(acc2[0], Ah, Bh0); mma_fp16(acc2[1], Ah, Bh0 + 2);
            mma_fp16(acc2[2], Ah, Bh1); mma_fp16(acc2[3], Ah, Bh1 + 2);
        }
        if (ch < 3) { CP_WAIT0(); }
        __syncthreads();
    }

    float* scp = (float*)(smem + SC_OFF);
#pragma unroll
    for (int nt = 0; nt < 4; nt++) {
        int col = ng * 32 + nt * 8 + 2 * (lane & 3);
        int r0 = mg * 16 + (lane >> 2);
        scp[r0 * 68 + col]           = acc2[nt][0] * 0.0625f;
        scp[r0 * 68 + col + 1]       = acc2[nt][1] * 0.0625f;
        scp[(r0 + 8) * 68 + col]     = acc2[nt][2] * 0.0625f;
        scp[(r0 + 8) * 68 + col + 1] = acc2[nt][3] * 0.0625f;
    }

    float* dfp = (float*)(smem + DF_OFF);
    float* wgt = (float*)(smem + WGT_OFF);
    float* xwp = (float*)(smem + XWP_OFF);
    if (tid < 64) {
        int mode = g_mode;
        size_t mi = (size_t)n * 64 + tid;
        bool at;
        if (mode == 0)      at = ((const int*)mask)[mi] != 0;
        else if (mode == 1) at = ((const uint8_t*)mask)[mi] != 0;
        else                at = ((const float*)mask)[mi] != 0.f;
        dfp[tid] = at ? 0.f : 1.f;
        wgt[tid] = 0.f;
    }
    __syncthreads();

    {
        const bool dk0 = dfp[lane] > 0.5f, dk1 = dfp[lane + 32] > 0.5f;
        float wa0 = 0.f, wa1 = 0.f;
#pragma unroll
        for (int r = 0; r < 8; r++) {
            int lq = w * 8 + r;
            bool dq = dfp[lq] > 0.5f;
            float s0 = scp[lq * 68 + lane], s1 = scp[lq * 68 + lane + 32];
            if (dq && dk0) s0 = -1e30f;
            if (dq && dk1) s1 = -1e30f;
            float m = fmaxf(s0, s1);
#pragma unroll
            for (int o = 16; o; o >>= 1) m = fmaxf(m, __shfl_xor_sync(0xffffffffu, m, o));
            float e0 = __expf(s0 - m), e1 = __expf(s1 - m);
            float ss = e0 + e1;
#pragma unroll
            for (int o = 16; o; o >>= 1) ss += __shfl_xor_sync(0xffffffffu, ss, o);
            float inv = 1.f / ss;
            wa0 += e0 * inv;
            wa1 += e1 * inv;
        }
        atomicAdd(&wgt[lane], wa0);
        atomicAdd(&wgt[lane + 32], wa1);
    }
    __syncthreads();

    {
        const int c = tid & 127, kh = tid >> 7;
        float a0 = 0.f, a1 = 0.f;
#pragma unroll 8
        for (int kk = 0; kk < 32; kk++) {
            int k = kh * 32 + kk;
            uint32_t boff = (uint32_t)(k * 512 + ((4 * c) ^ ((k & 7) << 4)));
            __half2 hv = *(__half2*)(smem + XH_OFF + boff);
            float2 fv = __half22float2(hv);
            float wk = wgt[k];
            a0 += wk * fv.x;
            a1 += wk * fv.y;
        }
        xwp[kh * 256 + 2 * c]     = a0;
        xwp[kh * 256 + 2 * c + 1] = a1;
    }
    __syncthreads();
    g_xw[(size_t)n * 256 + tid] = xwp[tid] + xwp[256 + tid];
}

// -------- xg_gemm: 512 CTAs x 128 thr, 16 samples x 128 gates ---------------
__global__ void __launch_bounds__(128) xg_gemm() {
    __shared__ float As[32][20];    // [j][sample]
    __shared__ float Bs[32][132];   // [j][gate]
    const int tid = threadIdx.x;
    const int n0 = blockIdx.x * 16;
    const int sgrp = tid >> 5, ggrp = tid & 31;
    float acc[4][4];
#pragma unroll
    for (int si = 0; si < 4; si++)
#pragma unroll
        for (int gi = 0; gi < 4; gi++) acc[si][gi] = 0.f;

    for (int e0 = 0; e0 < 256; e0 += 32) {
        for (int l = tid; l < 512; l += 128) {
            int ss = l >> 5, jj = l & 31;
            As[jj][ss] = g_xw[(size_t)(n0 + ss) * 256 + e0 + jj];
        }
        for (int l = tid; l < 4096; l += 128) {
            int jj = l >> 7, g = l & 127;
            Bs[jj][g] = g_W2[(e0 + jj) * 128 + g];
        }
        __syncthreads();
#pragma unroll 8
        for (int jj = 0; jj < 32; jj++) {
            float4 av = *(float4*)&As[jj][sgrp * 4];
            float4 bv = *(float4*)&Bs[jj][ggrp * 4];
            float a[4] = {av.x, av.y, av.z, av.w};
            float bb[4] = {bv.x, bv.y, bv.z, bv.w};
#pragma unroll
            for (int si = 0; si < 4; si++)
#pragma unroll
                for (int gi = 0; gi < 4; gi++) acc[si][gi] += a[si] * bb[gi];
        }
        __syncthreads();
    }
#pragma unroll
    for (int si = 0; si < 4; si++)
#pragma unroll
        for (int gi = 0; gi < 4; gi++) {
            int g = ggrp * 4 + gi;
            g_xg[(size_t)(n0 + sgrp * 4 + si) * 128 + g] = acc[si][gi] + g_bias[g];
        }
}

// ------- LSTM: 1 env/block, 128 thr (gate-parallel), weights in registers ----
__device__ __forceinline__ float sigmoidf_(float v) { return 1.f / (1.f + __expf(-v)); }

__global__ void __launch_bounds__(128) lstm_kernel(const float* __restrict__ done,
                                                   const float* __restrict__ h0,
                                                   const float* __restrict__ c0,
                                                   const float* __restrict__ whh,
                                                   const float* __restrict__ cw,
                                                   const float* __restrict__ cb,
                                                   float* __restrict__ out) {
    __shared__ float hsm[32];        // h_{t-1}
    __shared__ float gs[4][32];      // activated gates i,f,g,o
    __shared__ float hist[64 * 33];  // h history for critic
    __shared__ float cws[32];
    const int tid = threadIdx.x, lane = tid & 31, w = tid >> 5;
    const int b = blockIdx.x;

    // thread (w, lane) owns gate row (w*32+lane): 32 contiguous weights -> regs
    float wreg[32];
    {
        const float4* wr = (const float4*)(whh + (size_t)(w * 32 + lane) * 32);
#pragma unroll
        for (int q = 0; q < 8; q++) {
            float4 v = wr[q];
            wreg[4 * q] = v.x; wreg[4 * q + 1] = v.y;
            wreg[4 * q + 2] = v.z; wreg[4 * q + 3] = v.w;
        }
    }
    if (tid < 32) { hsm[tid] = h0[b * H_DIM + tid]; cws[tid] = cw[tid]; }
    float c = c0[b * H_DIM + lane];  // every thread keeps lane's c (redundant copies)
    __syncthreads();

    float dn = done[b];
    float px = g_xg[(size_t)b * 128 + w * 32 + lane];

    for (int t = 0; t < T_STEPS; t++) {
        float xgv = px, dc = dn;
        if (t < 63) {
            int n2 = (t + 1) * B_ENV + b;
            dn = done[n2];
            px = g_xg[(size_t)n2 * 128 + w * 32 + lane];
        }
        float keep = 1.f - dc;
        float acc = 0.f;
#pragma unroll
        for (int m = 0; m < 32; m++) acc += hsm[m] * wreg[m];
        float gate = xgv + keep * acc;
        float act = (w == 2) ? tanhf(gate) : sigmoidf_(gate);
        gs[w][lane] = act;
        __syncthreads();
        float gi_ = gs[0][lane], gf_ = gs[1][lane], gg_ = gs[2][lane], go_ = gs[3][lane];
        c = gf_ * (c * keep) + gi_ * gg_;
        float h = go_ * tanhf(c);
        if (w == 0) { hsm[lane] = h; hist[t * 33 + lane] = h; }
        __syncthreads();
    }

    // critic: thread t<64 computes out[t]
    if (tid < 64) {
        float a = 0.f;
#pragma unroll 8
        for (int m = 0; m < 32; m++) a += hist[tid * 33 + m] * cws[m];
        out[tid * B_ENV + b] = a + cb[0];
    }
}

extern "C" void kernel_launch(void* const* d_in, const int* in_sizes, int n_in,
                              void* d_out, int out_size) {
    const float* x    = (const float*)d_in[0];
    const float* done = (const float*)d_in[1];
    const void*  mask = d_in[2];
    const float* h0   = (const float*)d_in[3];
    const float* c0   = (const float*)d_in[4];
    const float* ipw  = (const float*)d_in[5];
    const float* opw  = (const float*)d_in[6];
    const float* wih  = (const float*)d_in[7];
    const float* whh  = (const float*)d_in[8];
    const float* bih  = (const float*)d_in[9];
    const float* bhh  = (const float*)d_in[10];
    const float* cw   = (const float*)d_in[11];
    const float* cb   = (const float*)d_in[12];
    float*       out  = (float*)d_out;
    (void)in_sizes; (void)n_in; (void)out_size;

    cudaFuncSetAttribute(attn_mma, cudaFuncAttributeMaxDynamicSharedMemorySize, SMEM_SZ);
    prep1<<<128, 256>>>(ipw, opw);
    prep2<<<97, 256>>>(wih, bih, bhh, mask);
    attn_mma<<<N_TOT, 256, SMEM_SZ>>>(x, mask);
    xg_gemm<<<N_TOT / 16, 128>>>();
    lstm_kernel<<<B_ENV, 128>>>(done, h0, c0, whh, cw, cb, out);
}

// round 17
// speedup vs baseline: 1.0233x; 1.0233x over previous
#include <cuda_runtime.h>
#include <cuda_fp16.h>
#include <cstdint>

#define T_STEPS 64
#define B_ENV 128
#define L_TOK 64
#define E_DIM 256
#define H_DIM 32
#define N_TOT (T_STEPS * B_ENV)

__device__ float g_M[65536];
__device__ float g_WeffT[65536];
__device__ float g_W2[32768];
__device__ float g_bias[128];
__device__ unsigned short g_Mt16[65536]; // fp16 of M^T [j][i]
__device__ float g_xw[(size_t)N_TOT * 256]; // attention-pooled features
__device__ float g_xg[(size_t)N_TOT * 128];
__device__ int g_mode;

// ---------------- helpers ----------------
__device__ __forceinline__ uint32_t smem_u32(const void* p) {
    uint32_t a;
    asm("{ .reg .u64 t; cvta.to.shared.u64 t, %1; cvt.u32.u64 %0, t; }" : "=r"(a) : "l"(p));
    return a;
}
__device__ __forceinline__ void ldm4(uint32_t* r, uint32_t a) {
    asm volatile("ldmatrix.sync.aligned.m8n8.x4.shared.b16 {%0,%1,%2,%3}, [%4];"
        : "=r"(r[0]), "=r"(r[1]), "=r"(r[2]), "=r"(r[3]) : "r"(a));
}
__device__ __forceinline__ void mma_fp16(float* d, const uint32_t* a, const uint32_t* b) {
    asm volatile("mma.sync.aligned.m16n8k16.row.col.f32.f16.f16.f32 "
        "{%0,%1,%2,%3}, {%4,%5,%6,%7}, {%8,%9}, {%0,%1,%2,%3};"
        : "+f"(d[0]), "+f"(d[1]), "+f"(d[2]), "+f"(d[3])
        : "r"(a[0]), "r"(a[1]), "r"(a[2]), "r"(a[3]), "r"(b[0]), "r"(b[1]));
}
__device__ __forceinline__ uint32_t pack_h2(__half lo, __half hi) {
    __half2 p = __halves2half2(lo, hi);
    return *(uint32_t*)&p;
}
__device__ __forceinline__ void cp16(uint32_t dst, const void* src) {
    asm volatile("cp.async.cg.shared.global [%0], [%1], 16;" :: "r"(dst), "l"(src));
}
#define CP_COMMIT() asm volatile("cp.async.commit_group;" ::: "memory")
#define CP_WAIT0()  asm volatile("cp.async.wait_group 0;" ::: "memory")

// ---------------- prep1: M (b<64), WeffT (b>=64) ----------------
__global__ void __launch_bounds__(256) prep1(const float* __restrict__ ipw, const float* __restrict__ opw) {
    __shared__ float As[32][33], Bs[32][33];
    const int b = blockIdx.x, tid = threadIdx.x, tx = tid & 31, ty = tid >> 5;
    float acc[4] = {0.f, 0.f, 0.f, 0.f};
    if (b < 64) {
        int i0 = (b >> 3) * 32, j0 = (b & 7) * 32;
        const float *Wq = ipw, *Wk = ipw + 65536;
        for (int e0 = 0; e0 < 256; e0 += 32) {
#pragma unroll
            for (int r = 0; r < 4; r++) {
                int e = ty + 8 * r;
                As[e][tx] = Wq[(e0 + e) * 256 + i0 + tx];
                Bs[e][tx] = Wk[(e0 + e) * 256 + j0 + tx];
            }
            __syncthreads();
#pragma unroll 8
            for (int e = 0; e < 32; e++) {
                float bv = Bs[e][tx];
#pragma unroll
                for (int r = 0; r < 4; r++) acc[r] += As[e][ty + 8 * r] * bv;
            }
            __syncthreads();
        }
#pragma unroll
        for (int r = 0; r < 4; r++) g_M[(i0 + ty + 8 * r) * 256 + j0 + tx] = acc[r];
    } else {
        int t = b - 64, j0 = (t >> 3) * 32, f0 = (t & 7) * 32;
        const float* Wv = ipw + 131072;
        for (int e0 = 0; e0 < 256; e0 += 32) {
#pragma unroll
            for (int r = 0; r < 4; r++) {
                int e = ty + 8 * r;
                As[e][tx] = Wv[(e0 + e) * 256 + j0 + tx];
                Bs[tx][e] = opw[(f0 + e) * 256 + e0 + tx];
            }
            __syncthreads();
#pragma unroll 8
            for (int e = 0; e < 32; e++) {
                float bv = Bs[e][tx];
#pragma unroll
                for (int r = 0; r < 4; r++) acc[r] += As[e][ty + 8 * r] * bv;
            }
            __syncthreads();
        }
#pragma unroll
        for (int r = 0; r < 4; r++) g_WeffT[(j0 + ty + 8 * r) * 256 + f0 + tx] = acc[r];
    }
}

// ------- prep2: Mt fp16 (b<64), W2 (64..95), bias + mask-mode (96) -------
__global__ void __launch_bounds__(256) prep2(const float* __restrict__ wih,
                                             const float* __restrict__ bih,
                                             const float* __restrict__ bhh,
                                             const void* __restrict__ mask) {
    __shared__ float As[32][33], Bs[32][33];
    const int b = blockIdx.x, tid = threadIdx.x, tx = tid & 31, ty = tid >> 5;
    if (b < 64) {
        int i0 = (b >> 3) * 32, j0 = (b & 7) * 32;
#pragma unroll
        for (int r = 0; r < 4; r++) As[ty + 8 * r][tx] = g_M[(i0 + ty + 8 * r) * 256 + j0 + tx];
        __syncthreads();
#pragma unroll
        for (int r = 0; r < 4; r++) {
            int jj = ty + 8 * r;
            __half h = __float2half_rn(As[tx][jj]);
            g_Mt16[(j0 + jj) * 256 + i0 + tx] = *(unsigned short*)&h;
        }
        return;
    }
    if (b < 96) {
        int t = b - 64, j0 = (t >> 2) * 32, g0 = (t & 3) * 32;
        float acc[4] = {0.f, 0.f, 0.f, 0.f};
        for (int f0 = 0; f0 < 256; f0 += 32) {
#pragma unroll
            for (int r = 0; r < 4; r++) {
                int e = ty + 8 * r;
                As[tx][e] = g_WeffT[(j0 + e) * 256 + f0 + tx];
                Bs[tx][e] = wih[(g0 + e) * 256 + f0 + tx];
            }
            __syncthreads();
#pragma unroll 8
            for (int f = 0; f < 32; f++) {
                float bv = Bs[f][tx];
#pragma unroll
                for (int r = 0; r < 4; r++) acc[r] += As[f][ty + 8 * r] * bv;
            }
            __syncthreads();
        }
#pragma unroll
        for (int r = 0; r < 4; r++) g_W2[(j0 + ty + 8 * r) * 128 + g0 + tx] = acc[r];
        return;
    }
    if (tid < 128) g_bias[tid] = bih[tid] + bhh[tid];
    __shared__ int sf, sg;
    if (!tid) { sf = 0; sg = 0; }
    __syncthreads();
    const unsigned* mw = (const unsigned*)mask;
    int f = 0, g = 0;
    for (int i = tid; i < 4096; i += 256) {
        unsigned v = mw[i];
        if (v == 0x3F800000u) f = 1;
        if (v > 1u) g = 1;
    }
    if (f) atomicOr(&sf, 1);
    if (g) atomicOr(&sg, 1);
    __syncthreads();
    if (!tid) g_mode = sf ? 2 : (sg ? 1 : 0);
}

// ---------------- attention: full fp16, 1 sample/CTA, 3 CTAs/SM --------------
#define XH_OFF   0        /* x fp16: 64 x 512 */
#define STG_OFF  32768    /* Mt16 chunk: 64 x 512 */
#define TSH_OFF  65536    /* ts fp16: 64 x 128 */
#define SMEM_SZ  73728
#define SC_OFF   STG_OFF           /* f32 [64][68] after GEMMs */
#define DF_OFF   TSH_OFF           /* 64 f */
#define WGT_OFF  (TSH_OFF + 256)   /* 64 f */
#define XWP_OFF  (TSH_OFF + 2048)  /* 512 f partials */

__global__ void __launch_bounds__(256, 3) attn_mma(const float* __restrict__ x,
                                                   const void* __restrict__ mask) {
    extern __shared__ char smem[];
    const uint32_t sb = smem_u32(smem);
    const int tid = threadIdx.x, lane = tid & 31, w = tid >> 5;
    const int n = blockIdx.x;

    for (int u = tid; u < 2048; u += 256) {
        int row = u >> 5, c16 = (u & 31) << 4;
        uint32_t d = STG_OFF + row * 512 + (c16 ^ ((row & 7) << 4));
        cp16(sb + d, (const uint4*)g_Mt16 + u);
    }
    CP_COMMIT();

    const float2* xb = (const float2*)(x + (size_t)n * (L_TOK * E_DIM));
    for (int idx = tid; idx < 8192; idx += 256) {
        int r = idx >> 7, cp = idx & 127;
        float2 v = xb[idx];
        uint32_t boff = (uint32_t)(r * 512 + ((cp * 4) ^ ((r & 7) << 4)));
        *(uint32_t*)(smem + XH_OFF + boff) =
            pack_h2(__float2half_rn(v.x), __float2half_rn(v.y));
    }
    CP_WAIT0();
    __syncthreads();

    const int mg = w >> 1, ng = w & 1;
    const int arow = mg * 16 + (lane & 15);
    const uint32_t a_rot = (arow & 7) << 4, a_klo = (lane >> 4) << 4;
    const uint32_t axh = sb + XH_OFF + arow * 512;
    const uint32_t ath = sb + TSH_OFF + arow * 128;
    const int br0 = ng * 32 + (lane & 7) + ((lane & 16) >> 1), br1 = br0 + 16;
    const uint32_t b_rot0 = (br0 & 7) << 4, b_rot1 = (br1 & 7) << 4;
    const uint32_t bklo = ((lane >> 3) & 1) << 4;

    float acc2[4][4];
#pragma unroll
    for (int nt = 0; nt < 4; nt++)
#pragma unroll
        for (int q = 0; q < 4; q++) acc2[nt][q] = 0.f;

    for (int ch = 0; ch < 4; ch++) {
        float acc1[4][4];
#pragma unroll
        for (int nt = 0; nt < 4; nt++)
#pragma unroll
            for (int q = 0; q < 4; q++) acc1[nt][q] = 0.f;
        const uint32_t sg0 = sb + STG_OFF + br0 * 512, sg1 = sb + STG_OFF + br1 * 512;
#pragma unroll 4
        for (int ks = 0; ks < 16; ks++) {
            uint32_t kb = ks * 32;
            uint32_t Ah[4], B0[4], B1[4];
            ldm4(Ah, axh + ((kb + a_klo) ^ a_rot));
            ldm4(B0, sg0 + ((kb + bklo) ^ b_rot0));
            ldm4(B1, sg1 + ((kb + bklo) ^ b_rot1));
            mma_fp16(acc1[0], Ah, B0); mma_fp16(acc1[1], Ah, B0 + 2);
            mma_fp16(acc1[2], Ah, B1); mma_fp16(acc1[3], Ah, B1 + 2);
        }
#pragma unroll
        for (int nt = 0; nt < 4; nt++) {
            int col = ng * 32 + nt * 8 + 2 * (lane & 3);
            int r0 = mg * 16 + (lane >> 2);
#pragma unroll
            for (int hh = 0; hh < 2; hh++) {
                int rr = r0 + 8 * hh;
                uint32_t boff = (uint32_t)(rr * 128 + ((col * 2) ^ ((rr & 7) << 4)));
                *(uint32_t*)(smem + TSH_OFF + boff) =
                    pack_h2(__float2half_rn(acc1[nt][2 * hh]),
                            __float2half_rn(acc1[nt][2 * hh + 1]));
            }
        }
        __syncthreads();

        if (ch < 3) {
            for (int u = tid; u < 2048; u += 256) {
                int row = u >> 5, c16 = (u & 31) << 4;
                uint32_t d = STG_OFF + row * 512 + (c16 ^ ((row & 7) << 4));
                cp16(sb + d, (const uint4*)(g_Mt16 + (ch + 1) * 16384) + u);
            }
            CP_COMMIT();
        }

        const uint32_t bxh0 = sb + XH_OFF + br0 * 512, bxh1 = sb + XH_OFF + br1 * 512;
#pragma unroll
        for (int ks = 0; ks < 4; ks++) {
            uint32_t kb = ks * 32, xc = ch * 128 + kb + bklo;
            uint32_t Ah[4], Bh0[4], Bh1[4];
            ldm4(Ah, ath + ((kb + a_klo) ^ a_rot));
            ldm4(Bh0, bxh0 + (xc ^ b_rot0));
            ldm4(Bh1, bxh1 + (xc ^ b_rot1));
            mma_fp16(acc2[0], Ah, Bh0); mma_fp16(acc2[1], Ah, Bh0 + 2);
            mma_fp16(acc2[2], Ah, Bh1); mma_fp16(acc2[3], Ah, Bh1 + 2);
        }
        if (ch < 3) { CP_WAIT0(); }
        __syncthreads();
    }

    float* scp = (float*)(smem + SC_OFF);
#pragma unroll
    for (int nt = 0; nt < 4; nt++) {
        int col = ng * 32 + nt * 8 + 2 * (lane & 3);
        int r0 = mg * 16 + (lane >> 2);
        scp[r0 * 68 + col]           = acc2[nt][0] * 0.0625f;
        scp[r0 * 68 + col + 1]       = acc2[nt][1] * 0.0625f;
        scp[(r0 + 8) * 68 + col]     = acc2[nt][2] * 0.0625f;
        scp[(r0 + 8) * 68 + col + 1] = acc2[nt][3] * 0.0625f;
    }

    float* dfp = (float*)(smem + DF_OFF);
    float* wgt = (float*)(smem + WGT_OFF);
    float* xwp = (float*)(smem + XWP_OFF);
    if (tid < 64) {
        int mode = g_mode;
        size_t mi = (size_t)n * 64 + tid;
        bool at;
        if (mode == 0)      at = ((const int*)mask)[mi] != 0;
        else if (mode == 1) at = ((const uint8_t*)mask)[mi] != 0;
        else                at = ((const float*)mask)[mi] != 0.f;
        dfp[tid] = at ? 0.f : 1.f;
        wgt[tid] = 0.f;
    }
    __syncthreads();

    {
        const bool dk0 = dfp[lane] > 0.5f, dk1 = dfp[lane + 32] > 0.5f;
        float wa0 = 0.f, wa1 = 0.f;
#pragma unroll
        for (int r = 0; r < 8; r++) {
            int lq = w * 8 + r;
            bool dq = dfp[lq] > 0.5f;
            float s0 = scp[lq * 68 + lane], s1 = scp[lq * 68 + lane + 32];
            if (dq && dk0) s0 = -1e30f;
            if (dq && dk1) s1 = -1e30f;
            float m = fmaxf(s0, s1);
#pragma unroll
            for (int o = 16; o; o >>= 1) m = fmaxf(m, __shfl_xor_sync(0xffffffffu, m, o));
            float e0 = __expf(s0 - m), e1 = __expf(s1 - m);
            float ss = e0 + e1;
#pragma unroll
            for (int o = 16; o; o >>= 1) ss += __shfl_xor_sync(0xffffffffu, ss, o);
            float inv = 1.f / ss;
            wa0 += e0 * inv;
            wa1 += e1 * inv;
        }
        atomicAdd(&wgt[lane], wa0);
        atomicAdd(&wgt[lane + 32], wa1);
    }
    __syncthreads();

    {
        const int c = tid & 127, kh = tid >> 7;
        float a0 = 0.f, a1 = 0.f;
#pragma unroll 8
        for (int kk = 0; kk < 32; kk++) {
            int k = kh * 32 + kk;
            uint32_t boff = (uint32_t)(k * 512 + ((4 * c) ^ ((k & 7) << 4)));
            __half2 hv = *(__half2*)(smem + XH_OFF + boff);
            float2 fv = __half22float2(hv);
            float wk = wgt[k];
            a0 += wk * fv.x;
            a1 += wk * fv.y;
        }
        xwp[kh * 256 + 2 * c]     = a0;
        xwp[kh * 256 + 2 * c + 1] = a1;
    }
    __syncthreads();
    g_xw[(size_t)n * 256 + tid] = xwp[tid] + xwp[256 + tid];
}

// -------- xg_gemm: R15 config (256 CTAs x 256 thr, 32 samples) --------------
__global__ void __launch_bounds__(256) xg_gemm() {
    __shared__ float As[32][36];    // [j][sample]
    __shared__ float Bs[32][132];   // [j][gate]
    const int tid = threadIdx.x;
    const int n0 = blockIdx.x * 32;
    const int sgrp = tid >> 5, ggrp = tid & 31;
    float acc[4][4];
#pragma unroll
    for (int si = 0; si < 4; si++)
#pragma unroll
        for (int gi = 0; gi < 4; gi++) acc[si][gi] = 0.f;

    for (int e0 = 0; e0 < 256; e0 += 32) {
        for (int l = tid; l < 1024; l += 256) {
            int ss = l >> 5, jj = l & 31;
            As[jj][ss] = g_xw[(size_t)(n0 + ss) * 256 + e0 + jj];
        }
        for (int l = tid; l < 4096; l += 256) {
            int jj = l >> 7, g = l & 127;
            Bs[jj][g] = g_W2[(e0 + jj) * 128 + g];
        }
        __syncthreads();
#pragma unroll 8
        for (int jj = 0; jj < 32; jj++) {
            float4 av = *(float4*)&As[jj][sgrp * 4];
            float4 bv = *(float4*)&Bs[jj][ggrp * 4];
            float a[4] = {av.x, av.y, av.z, av.w};
            float bb[4] = {bv.x, bv.y, bv.z, bv.w};
#pragma unroll
            for (int si = 0; si < 4; si++)
#pragma unroll
                for (int gi = 0; gi < 4; gi++) acc[si][gi] += a[si] * bb[gi];
        }
        __syncthreads();
    }
#pragma unroll
    for (int si = 0; si < 4; si++)
#pragma unroll
        for (int gi = 0; gi < 4; gi++) {
            int g = ggrp * 4 + gi;
            g_xg[(size_t)(n0 + sgrp * 4 + si) * 128 + g] = acc[si][gi] + g_bias[g];
        }
}

// ------- LSTM: 1 env/block, 128 thr (gate-parallel), weights in registers ----
__device__ __forceinline__ float sigmoidf_(float v) { return 1.f / (1.f + __expf(-v)); }

__global__ void __launch_bounds__(128) lstm_kernel(const float* __restrict__ done,
                                                   const float* __restrict__ h0,
                                                   const float* __restrict__ c0,
                                                   const float* __restrict__ whh,
                                                   const float* __restrict__ cw,
                                                   const float* __restrict__ cb,
                                                   float* __restrict__ out) {
    __shared__ float hsm[32];        // h_{t-1}
    __shared__ float gs[4][32];      // activated gates i,f,g,o
    __shared__ float hist[64 * 33];  // h history for critic
    __shared__ float cws[32];
    const int tid = threadIdx.x, lane = tid & 31, w = tid >> 5;
    const int b = blockIdx.x;

    float wreg[32];
    {
        const float4* wr = (const float4*)(whh + (size_t)(w * 32 + lane) * 32);
#pragma unroll
        for (int q = 0; q < 8; q++) {
            float4 v = wr[q];
            wreg[4 * q] = v.x; wreg[4 * q + 1] = v.y;
            wreg[4 * q + 2] = v.z; wreg[4 * q + 3] = v.w;
        }
    }
    if (tid < 32) { hsm[tid] = h0[b * H_DIM + tid]; cws[tid] = cw[tid]; }
    float c = c0[b * H_DIM + lane];
    __syncthreads();

    float dn = done[b];
    float px = g_xg[(size_t)b * 128 + w * 32 + lane];

    for (int t = 0; t < T_STEPS; t++) {
        float xgv = px, dc = dn;
        if (t < 63) {
            int n2 = (t + 1) * B_ENV + b;
            dn = done[n2];
            px = g_xg[(size_t)n2 * 128 + w * 32 + lane];
        }
        float keep = 1.f - dc;
        float acc = 0.f;
#pragma unroll
        for (int m = 0; m < 32; m++) acc += hsm[m] * wreg[m];
        float gate = xgv + keep * acc;
        float act = (w == 2) ? tanhf(gate) : sigmoidf_(gate);
        gs[w][lane] = act;
        __syncthreads();
        float gi_ = gs[0][lane], gf_ = gs[1][lane], gg_ = gs[2][lane], go_ = gs[3][lane];
        c = gf_ * (c * keep) + gi_ * gg_;
        float h = go_ * tanhf(c);
        if (w == 0) { hsm[lane] = h; hist[t * 33 + lane] = h; }
        __syncthreads();
    }

    if (tid < 64) {
        float a = 0.f;
#pragma unroll 8
        for (int m = 0; m < 32; m++) a += hist[tid * 33 + m] * cws[m];
        out[tid * B_ENV + b] = a + cb[0];
    }
}

extern "C" void kernel_launch(void* const* d_in, const int* in_sizes, int n_in,
                              void* d_out, int out_size) {
    const float* x    = (const float*)d_in[0];
    const float* done = (const float*)d_in[1];
    const void*  mask = d_in[2];
    const float* h0   = (const float*)d_in[3];
    const float* c0   = (const float*)d_in[4];
    const float* ipw  = (const float*)d_in[5];
    const float* opw  = (const float*)d_in[6];
    const float* wih  = (const float*)d_in[7];
    const float* whh  = (const float*)d_in[8];
    const float* bih  = (const float*)d_in[9];
    const float* bhh  = (const float*)d_in[10];
    const float* cw   = (const float*)d_in[11];
    const float* cb   = (const float*)d_in[12];
    float*       out  = (float*)d_out;
    (void)in_sizes; (void)n_in; (void)out_size;

    cudaFuncSetAttribute(attn_mma, cudaFuncAttributeMaxDynamicSharedMemorySize, SMEM_SZ);
    prep1<<<128, 256>>>(ipw, opw);
    prep2<<<97, 256>>>(wih, bih, bhh, mask);
    attn_mma<<<N_TOT, 256, SMEM_SZ>>>(x, mask);
    xg_gemm<<<N_TOT / 32, 256>>>();
    lstm_kernel<<<B_ENV, 128>>>(done, h0, c0, whh, cw, cb, out);
}